// round 1
// baseline (speedup 1.0000x reference)
#include <cuda_runtime.h>
#include <math.h>

#define NN 50000
#define D 128
#define LAY 3
#define RK 16
#define NE 1600000

// ---------------- static device scratch (no allocations allowed) ----------------
static __device__ int d_cnt[NN];
static __device__ int d_rowptr[NN + 1];
static __device__ int d_cursor[NN];
static __device__ int d_scol[NE];
static __device__ __align__(16) float d_sval[NE];
static __device__ __align__(16) float d_h[NN * D];     // current layer output
static __device__ __align__(16) float d_agg[NN * D];   // spmm output
static __device__ __align__(16) float d_zsum[D];       // running column sums of h_bar numerator
static __device__ __align__(16) float d_hz[D];
static __device__ __align__(16) float d_wcol[RK * D];

// ---------------- CSR build ----------------
__global__ void k_zero() {
    int i = blockIdx.x * blockDim.x + threadIdx.x;
    if (i < NN) d_cnt[i] = 0;
    if (i < D) d_zsum[i] = 0.f;
}

__global__ void k_hist(const int* __restrict__ rows) {
    int e = blockIdx.x * blockDim.x + threadIdx.x;
    if (e < NE) atomicAdd(&d_cnt[rows[e]], 1);
}

// single-block exclusive scan over 50000 counts
__global__ void k_scan() {
    __shared__ int s[1024];
    int t = threadIdx.x;
    int carry = 0;
    for (int base = 0; base < NN; base += 1024) {
        int i = base + t;
        int v = (i < NN) ? d_cnt[i] : 0;
        s[t] = v;
        __syncthreads();
        for (int off = 1; off < 1024; off <<= 1) {
            int a = (t >= off) ? s[t - off] : 0;
            __syncthreads();
            s[t] += a;
            __syncthreads();
        }
        int excl = s[t] - v;
        if (i < NN) { d_rowptr[i] = carry + excl; d_cursor[i] = carry + excl; }
        int tot = s[1023];
        __syncthreads();
        carry += tot;
    }
    if (t == 0) d_rowptr[NN] = carry;
}

__global__ void k_scatter(const int* __restrict__ rows, const int* __restrict__ cols,
                          const float* __restrict__ vals) {
    int e = blockIdx.x * blockDim.x + threadIdx.x;
    if (e < NE) {
        int p = atomicAdd(&d_cursor[rows[e]], 1);
        d_scol[p] = cols[e];
        d_sval[p] = vals[e];
    }
}

// ---------------- column sums of node_feats into zsum ----------------
__global__ void k_colsum(const float* __restrict__ x) {
    int dcol = threadIdx.x;           // 128 threads
    int r0 = blockIdx.x * 256;
    int r1 = min(r0 + 256, NN);
    float s = 0.f;
    for (int r = r0; r < r1; r++) s += x[(size_t)r * D + dcol];
    atomicAdd(&d_zsum[dcol], s);
}

// ---------------- SpMM: warp per row, pull mode ----------------
__global__ void k_spmm(const float* __restrict__ hin) {
    int w = (blockIdx.x * blockDim.x + threadIdx.x) >> 5;
    int lane = threadIdx.x & 31;
    if (w >= NN) return;
    int e0 = d_rowptr[w], e1 = d_rowptr[w + 1];
    float4 acc = make_float4(0.f, 0.f, 0.f, 0.f);
    for (int e = e0; e < e1; e += 32) {
        int cnt = min(32, e1 - e);
        int myc = 0; float myv = 0.f;
        if (lane < cnt) { myc = d_scol[e + lane]; myv = d_sval[e + lane]; }
        #pragma unroll 4
        for (int j = 0; j < cnt; j++) {
            int   c = __shfl_sync(0xffffffffu, myc, j);
            float v = __shfl_sync(0xffffffffu, myv, j);
            float4 hv = *(const float4*)(hin + (size_t)c * D + lane * 4);
            acc.x += v * hv.x; acc.y += v * hv.y; acc.z += v * hv.z; acc.w += v * hv.w;
        }
    }
    *(float4*)(d_agg + (size_t)w * D + lane * 4) = acc;
}

// ---------------- GEMM: h = elu(agg @ W^T + b), epilogue accumulates column sums ----------------
// tile: 64 rows x 128 cols, 256 threads, microtile 4x8, K=128
#define GEMM_SMEM ((128 * 68 + 128 * 132 + 16 * 128) * 4)

__global__ void k_gemm(const float* __restrict__ A, const float* __restrict__ W,
                       const float* __restrict__ b) {
    extern __shared__ float sm[];
    float (*At)[68]  = (float (*)[68])sm;                       // [k][r] transposed, padded
    float (*Wt)[132] = (float (*)[132])(sm + 128 * 68);         // [k][n] transposed, padded
    float (*sp)[128] = (float (*)[128])(sm + 128 * 68 + 128 * 132);

    int tid = threadIdx.x;
    int rb = blockIdx.x * 64;

    // load A tile transposed (guard rows >= NN with zeros)
    #pragma unroll
    for (int t = 0; t < 8; t++) {
        int idx = tid + t * 256;
        int row = idx >> 5, kq = idx & 31;
        int ri = rb + row;
        float4 v = make_float4(0.f, 0.f, 0.f, 0.f);
        if (ri < NN) v = *(const float4*)(A + (size_t)ri * D + kq * 4);
        At[kq * 4 + 0][row] = v.x; At[kq * 4 + 1][row] = v.y;
        At[kq * 4 + 2][row] = v.z; At[kq * 4 + 3][row] = v.w;
    }
    // load W transposed: Wt[k][n] = W[n][k]
    #pragma unroll
    for (int t = 0; t < 16; t++) {
        int idx = tid + t * 256;
        int n = idx >> 5, kq = idx & 31;
        float4 v = *(const float4*)(W + n * D + kq * 4);
        Wt[kq * 4 + 0][n] = v.x; Wt[kq * 4 + 1][n] = v.y;
        Wt[kq * 4 + 2][n] = v.z; Wt[kq * 4 + 3][n] = v.w;
    }
    __syncthreads();

    int ty = tid >> 4, tx = tid & 15;
    int r0 = ty * 4, n0 = tx * 8;

    float acc[4][8];
    #pragma unroll
    for (int i = 0; i < 4; i++)
        #pragma unroll
        for (int j = 0; j < 8; j++) acc[i][j] = 0.f;

    #pragma unroll 8
    for (int k = 0; k < D; k++) {
        float4 a  = *(float4*)&At[k][r0];
        float4 b0 = *(float4*)&Wt[k][n0];
        float4 b1 = *(float4*)&Wt[k][n0 + 4];
        float av[4] = {a.x, a.y, a.z, a.w};
        float bv[8] = {b0.x, b0.y, b0.z, b0.w, b1.x, b1.y, b1.z, b1.w};
        #pragma unroll
        for (int i = 0; i < 4; i++)
            #pragma unroll
            for (int j = 0; j < 8; j++) acc[i][j] += av[i] * bv[j];
    }

    float4 bb0 = *(const float4*)(b + n0);
    float4 bb1 = *(const float4*)(b + n0 + 4);
    float bvv[8] = {bb0.x, bb0.y, bb0.z, bb0.w, bb1.x, bb1.y, bb1.z, bb1.w};
    float csum[8] = {0.f, 0.f, 0.f, 0.f, 0.f, 0.f, 0.f, 0.f};

    #pragma unroll
    for (int i = 0; i < 4; i++) {
        int ri = rb + r0 + i;
        if (ri < NN) {
            float o[8];
            #pragma unroll
            for (int j = 0; j < 8; j++) {
                float tt = acc[i][j] + bvv[j];
                o[j] = tt > 0.f ? tt : (expf(tt) - 1.f);   // ELU
                csum[j] += o[j];
            }
            *(float4*)(d_h + (size_t)ri * D + n0)     = make_float4(o[0], o[1], o[2], o[3]);
            *(float4*)(d_h + (size_t)ri * D + n0 + 4) = make_float4(o[4], o[5], o[6], o[7]);
        }
    }
    #pragma unroll
    for (int j = 0; j < 8; j++) sp[ty][n0 + j] = csum[j];
    __syncthreads();
    if (tid < D) {
        float tot = 0.f;
        #pragma unroll
        for (int q = 0; q < 16; q++) tot += sp[q][tid];
        atomicAdd(&d_zsum[tid], tot);
    }
}

// ---------------- z -> hz (leaky relu matvec), single block ----------------
__global__ void k_zhz(const float* __restrict__ fc1W, const float* __restrict__ fc1b) {
    __shared__ float zs[D];
    int dcol = threadIdx.x;
    zs[dcol] = d_zsum[dcol] * (1.0f / ((float)(LAY + 1) * (float)NN));
    __syncthreads();
    float s = fc1b[dcol];
    #pragma unroll 8
    for (int k = 0; k < D; k++) s += zs[k] * fc1W[dcol * D + k];
    d_hz[dcol] = s > 0.f ? s : 0.2f * s;
}

// ---------------- W_col = hz @ fccol_W^T + b (2048 outputs, warp per output) ----------------
__global__ void k_wcolk(const float* __restrict__ Wc, const float* __restrict__ bc) {
    int gw = (blockIdx.x * blockDim.x + threadIdx.x) >> 5;
    int lane = threadIdx.x & 31;
    float4 hz4 = *(const float4*)(d_hz + lane * 4);
    for (int j = gw; j < RK * D; j += 512) {
        float4 w = *(const float4*)(Wc + (size_t)j * D + lane * 4);
        float p = hz4.x * w.x + hz4.y * w.y + hz4.z * w.z + hz4.w * w.w;
        #pragma unroll
        for (int o = 16; o > 0; o >>= 1) p += __shfl_xor_sync(0xffffffffu, p, o);
        if (lane == 0) d_wcol[j] = p + bc[j];
    }
}

// ---------------- fused: W_row GEMV (410MB stream) + W_u + elementwise update ----------------
__global__ void k_final(const float* __restrict__ Wr, const float* __restrict__ br,
                        const float* __restrict__ ini, float* __restrict__ out) {
    __shared__ float swc[RK][D];
    __shared__ float swr[8][RK];
    int tid = threadIdx.x;
    #pragma unroll
    for (int t = 0; t < 8; t++) {
        int idx = tid + t * 256;
        ((float*)swc)[idx] = d_wcol[idx];
    }
    int warp = tid >> 5, lane = tid & 31;
    float4 hz4 = *(const float4*)(d_hz + lane * 4);
    __syncthreads();

    int node = blockIdx.x * 8 + warp;          // 6250 blocks * 8 warps == 50000 exactly
    const float* wbase = Wr + (size_t)node * RK * D;
    #pragma unroll
    for (int r = 0; r < RK; r++) {
        float4 w = *(const float4*)(wbase + (size_t)r * D + lane * 4);
        float p = hz4.x * w.x + hz4.y * w.y + hz4.z * w.z + hz4.w * w.w;
        #pragma unroll
        for (int o = 16; o > 0; o >>= 1) p += __shfl_xor_sync(0xffffffffu, p, o);
        if (lane == 0) swr[warp][r] = p + br[(size_t)node * RK + r];
    }
    __syncwarp();

    float4 wu = make_float4(0.f, 0.f, 0.f, 0.f);
    #pragma unroll
    for (int r = 0; r < RK; r++) {
        float wr_ = swr[warp][r];
        float4 wc = *(const float4*)&swc[r][lane * 4];
        wu.x += wr_ * wc.x; wu.y += wr_ * wc.y; wu.z += wr_ * wc.z; wu.w += wr_ * wc.w;
    }
    float4 iv = *(const float4*)(ini + (size_t)node * D + lane * 4);
    float4 ov;
    ov.x = iv.x + wu.x * iv.x;
    ov.y = iv.y + wu.y * iv.y;
    ov.z = iv.z + wu.z * iv.z;
    ov.w = iv.w + wu.w * iv.w;
    *(float4*)(out + (size_t)node * D + lane * 4) = ov;
}

// ---------------- launch ----------------
extern "C" void kernel_launch(void* const* d_in, const int* in_sizes, int n_in,
                              void* d_out, int out_size) {
    const int*   rows  = (const int*)d_in[0];
    const int*   cols  = (const int*)d_in[1];
    const float* vals  = (const float*)d_in[2];
    const float* feats = (const float*)d_in[3];
    const float* gW    = (const float*)d_in[4];
    const float* gb    = (const float*)d_in[5];
    const float* fc1W  = (const float*)d_in[6];
    const float* fc1b  = (const float*)d_in[7];
    const float* frW   = (const float*)d_in[8];
    const float* frb   = (const float*)d_in[9];
    const float* fcW   = (const float*)d_in[10];
    const float* fcb   = (const float*)d_in[11];
    const float* ini   = (const float*)d_in[12];
    float* out = (float*)d_out;

    cudaFuncSetAttribute(k_gemm, cudaFuncAttributeMaxDynamicSharedMemorySize, GEMM_SMEM);

    k_zero<<<196, 256>>>();
    k_hist<<<6250, 256>>>(rows);
    k_scan<<<1, 1024>>>();
    k_scatter<<<6250, 256>>>(rows, cols, vals);
    k_colsum<<<196, 128>>>(feats);

    for (int l = 0; l < LAY; l++) {
        const float* hin = (l == 0) ? feats : d_h;
        k_spmm<<<6250, 256>>>(hin);
        k_gemm<<<782, 256, GEMM_SMEM>>>(d_agg, gW + (size_t)l * D * D, gb + (size_t)l * D);
    }

    k_zhz<<<1, 128>>>(fc1W, fc1b);
    k_wcolk<<<64, 256>>>(fcW, fcb);
    k_final<<<6250, 256>>>(frW, frb, ini, out);
}